// round 8
// baseline (speedup 1.0000x reference)
#include <cuda_runtime.h>
#include <cstdint>

#define B_    64
#define T_    512
#define H_    1024
#define D_    512
#define GB_   4     // batch groups
#define CPG_  32    // CTAs (chunks) per group
#define BPG_  16    // batches per group
#define CHPC_ 32    // channels per CTA
#define NCTA_ (GB_*CPG_)
#define NTHR_ 512
#define SLOTS_ 4

// scratch (static __device__ arrays: zero at module load, allocation-free)
__device__ float  g_u[(size_t)T_ * B_ * H_];           // u drive [t][b][h]
__device__ float  g_stt[SLOTS_][B_][H_];               // state slots (depth 4)
__device__ int    g_flag[T_ + 1][GB_][CPG_];           // monotonic chunk-ready counters (1/CTA/step)

// packed 2-wide fp32 FMA (sm_103a FFMA2, PTX-only)
__device__ __forceinline__ void fma2(unsigned long long& acc,
                                     unsigned long long a,
                                     unsigned long long b) {
    asm("fma.rn.f32x2 %0, %1, %2, %0;" : "+l"(acc) : "l"(a), "l"(b));
}
__device__ __forceinline__ float f2_lo(unsigned long long v) {
    return __uint_as_float((unsigned)(v & 0xffffffffull));
}
__device__ __forceinline__ float f2_hi(unsigned long long v) {
    return __uint_as_float((unsigned)(v >> 32));
}
__device__ __forceinline__ unsigned long long fdup(float x) {
    unsigned long long r;
    asm("mov.b64 %0, {%1, %1};" : "=l"(r) : "f"(x));
    return r;
}

// ---------------------------------------------------------------------------
// u[t][b][h] = sum_d x[b][t][d] * W_in[h][d] + b_in[h]  (f32x2 inner product)
// ---------------------------------------------------------------------------
__global__ __launch_bounds__(256) void u_gemm(const float* __restrict__ X,
                                              const float* __restrict__ Win,
                                              const float* __restrict__ bin) {
    __shared__ float As[8][128];
    __shared__ float Bs[8][128];
    int n0 = blockIdx.x * 128;
    int m0 = blockIdx.y * 128;
    int tid = threadIdx.x;
    int tm = tid >> 4, tn = tid & 15;

    unsigned long long acc2[8][4];
#pragma unroll
    for (int i = 0; i < 8; i++)
#pragma unroll
        for (int j = 0; j < 4; j++) acc2[i][j] = 0ull;

    int arow = tid >> 1;
    int ac4  = (tid & 1) * 4;
    const float* Aptr = X   + (size_t)(m0 + arow) * D_ + ac4;
    const float* Bptr = Win + (size_t)(n0 + arow) * D_ + ac4;

    for (int k0 = 0; k0 < D_; k0 += 8) {
        float4 av = *(const float4*)(Aptr + k0);
        float4 bv = *(const float4*)(Bptr + k0);
        As[ac4 + 0][arow] = av.x; As[ac4 + 1][arow] = av.y;
        As[ac4 + 2][arow] = av.z; As[ac4 + 3][arow] = av.w;
        Bs[ac4 + 0][arow] = bv.x; Bs[ac4 + 1][arow] = bv.y;
        Bs[ac4 + 2][arow] = bv.z; Bs[ac4 + 3][arow] = bv.w;
        __syncthreads();
#pragma unroll
        for (int kk = 0; kk < 8; kk++) {
            float rm[8];
            *(float4*)(rm)     = *(const float4*)&As[kk][tm * 8];
            *(float4*)(rm + 4) = *(const float4*)&As[kk][tm * 8 + 4];
            ulonglong2 t0 = *(const ulonglong2*)&Bs[kk][tn * 8];
            ulonglong2 t1 = *(const ulonglong2*)&Bs[kk][tn * 8 + 4];
            unsigned long long rnp[4] = {t0.x, t0.y, t1.x, t1.y};
#pragma unroll
            for (int i = 0; i < 8; i++) {
                unsigned long long rmd = fdup(rm[i]);
#pragma unroll
                for (int j = 0; j < 4; j++) fma2(acc2[i][j], rmd, rnp[j]);
            }
        }
        __syncthreads();
    }

    float bias[8];
    *(float4*)(bias)     = *(const float4*)&bin[n0 + tn * 8];
    *(float4*)(bias + 4) = *(const float4*)&bin[n0 + tn * 8 + 4];

#pragma unroll
    for (int i = 0; i < 8; i++) {
        int m  = m0 + tm * 8 + i;
        int tt = m & (T_ - 1);
        int bb = m >> 9;
        float* dst = g_u + ((size_t)tt * B_ + bb) * H_ + n0 + tn * 8;
        float4 v0, v1;
        v0.x = f2_lo(acc2[i][0]) + bias[0]; v0.y = f2_hi(acc2[i][0]) + bias[1];
        v0.z = f2_lo(acc2[i][1]) + bias[2]; v0.w = f2_hi(acc2[i][1]) + bias[3];
        v1.x = f2_lo(acc2[i][2]) + bias[4]; v1.y = f2_hi(acc2[i][2]) + bias[5];
        v1.z = f2_lo(acc2[i][3]) + bias[6]; v1.w = f2_hi(acc2[i][3]) + bias[7];
        *(float4*)(dst)     = v0;
        *(float4*)(dst + 4) = v1;
    }
}

// GEMM over one 256-k group of half h (round-5 inner loop, single Ssm buffer,
// row stride 1024)
#define GEMM_GROUP(hh, gsel)                                                    \
    {                                                                           \
        const float* wp = wb0 + ((hh) * 512 + (gsel) * 256);                    \
        const float* sbp = Ssm + bh * (8 * 1024) + (hh) * 512 + (gsel) * 256 + l * 4; \
        _Pragma("unroll")                                                       \
        for (int half_k = 0; half_k < 2; half_k++) {                            \
            ulonglong2 wv0 = *(const ulonglong2*)(wp + half_k * 128);           \
            ulonglong2 wv1 = *(const ulonglong2*)(wp + half_k * 128 + H_);      \
            ulonglong2 wv2 = *(const ulonglong2*)(wp + half_k * 128 + 2 * H_);  \
            ulonglong2 wv3 = *(const ulonglong2*)(wp + half_k * 128 + 3 * H_);  \
            _Pragma("unroll")                                                   \
            for (int b = 0; b < 8; b++) {                                       \
                ulonglong2 sv = *(const ulonglong2*)(sbp + b * 1024 + half_k * 128); \
                fma2(acc[b * 4 + 0], sv.x, wv0.x);                              \
                fma2(acc[b * 4 + 0], sv.y, wv0.y);                              \
                fma2(acc[b * 4 + 1], sv.x, wv1.x);                              \
                fma2(acc[b * 4 + 1], sv.y, wv1.y);                              \
                fma2(acc[b * 4 + 2], sv.x, wv2.x);                              \
                fma2(acc[b * 4 + 2], sv.y, wv2.y);                              \
                fma2(acc[b * 4 + 3], sv.x, wv3.x);                              \
                fma2(acc[b * 4 + 3], sv.y, wv3.y);                              \
            }                                                                   \
        }                                                                       \
    }

// ---------------------------------------------------------------------------
// Persistent recurrence kernel, 512 threads/CTA.
// CTA (g,jc): batches [16g,16g+16), channels [32jc,32jc+32).
// State tile staged in 2 halves of 512 k into one 64KB SMEM buffer; warp w
// stages batch w (free LN partials). 2 syncs + 1 tail sync per step.
// Flags: 1 atomic per CTA per step (round-5 protocol).
// ---------------------------------------------------------------------------
__global__ __launch_bounds__(512, 1) void rec_kernel(
    const float* __restrict__ Wst, const float* __restrict__ bst,
    const float* __restrict__ decay, const float* __restrict__ gamma,
    const float* __restrict__ beta, float* __restrict__ out) {
    extern __shared__ float smem[];
    float* Wsm   = smem;                    // [32][1024] = 32768 floats
    float* Ssm   = smem + CHPC_ * H_;       // [16][1024] = 16384 floats
    float* bcast = Ssm + BPG_ * H_;         // [16]x{mean,rstd} + epoch at [34]

    int g   = blockIdx.x / CPG_;
    int jc  = blockIdx.x % CPG_;
    int ch0 = jc * CHPC_;
    int b0  = g * BPG_;
    int tid = threadIdx.x;
    int w = tid >> 5, l = tid & 31;
    int cg = w & 7, bh = w >> 3;
    int seg = l;               // staging segment within batch row (batch = w)

    // load W_state slice (rows ch0..ch0+31)
    {
        const float4* src = (const float4*)(Wst + (size_t)ch0 * H_);
        float4* dst = (float4*)Wsm;
        for (int v = tid; v < CHPC_ * H_ / 4; v += NTHR_) dst[v] = __ldg(src + v);
    }

    // output ownership: lane l owns acc index l -> batch bh*8 + (l>>2), channel cg*4 + (l&3)
    int myb  = bh * 8 + (l >> 2);
    int gb   = b0 + myb;
    int mych = ch0 + cg * 4 + (l & 3);

    float dd = 1.0f / (1.0f + expf(-decay[mych]));
    float bs = bst[mych];
    float ga = gamma[mych], be = beta[mych];
    const unsigned FULL = 0xffffffffu;

    const float* wb0 = Wsm + (cg * 4) * H_ + l * 4;  // channel row base
    int fseg = seg >> 3;   // flag sub-index for staging load i: chunk = h*16 + i*4 + fseg
    int hA = jc >> 4;      // half containing own chunk (staged first)

    __syncthreads();

    float snp;   // my state value (channel mych, batch gb), register-resident
    int thr;     // flag threshold for this replay

    // ---------------- t = 0 : state is zero ----------------
    {
        float uv = __ldg(g_u + (size_t)gb * H_ + mych);
        snp = (1.0f - dd) * tanhf(uv + bs);
        __stcg(&g_stt[1][gb][mych], snp);
        __threadfence();
        __syncthreads();
        if (tid == 0) {
            int old = atomicAdd(&g_flag[1][g][jc], 1);
            bcast[34] = __int_as_float(old + 1);
        }
        __syncthreads();
        thr = __float_as_int(bcast[34]);
    }

    // ---------------- main loop t = 1..T-1 ----------------
    for (int t = 1; t < T_; ++t) {
        int slot  = t & 3;
        int wslot = (t + 1) & 3;
        float uv = __ldg(g_u + ((size_t)t * B_ + gb) * H_ + mych);

        unsigned long long acc[32];
#pragma unroll
        for (int o = 0; o < 32; o++) acc[o] = 0ull;

        float ln_s = 0.0f, ln_q = 0.0f;   // LN partials for batch w (state t-1)
        const float* srow = &g_stt[slot][b0 + w][0];   // my staging batch row

        // --- stage half hA (spin exact producer chunk, coalesced 512B/warp loads) ---
        {
#pragma unroll
            for (int i = 0; i < 4; i++) {
                volatile int* fp = &g_flag[t][g][hA * 16 + i * 4 + fseg];
                while (*fp < thr) {}
                float4 r = __ldcg((const float4*)(srow + hA * 512 + i * 128 + seg * 4));
                ln_s += r.x + r.y + r.z + r.w;
                ln_q += r.x*r.x + r.y*r.y + r.z*r.z + r.w*r.w;
                *(float4*)&Ssm[w * 1024 + hA * 512 + i * 128 + seg * 4] = r;
            }
        }
        __syncthreads();

        int hB = hA ^ 1;
        // spin + issue half-B loads (hidden under GEMM A-group0)
        float4 rb[4];
#pragma unroll
        for (int i = 0; i < 4; i++) {
            volatile int* fp = &g_flag[t][g][hB * 16 + i * 4 + fseg];
            while (*fp < thr) {}
            rb[i] = __ldcg((const float4*)(srow + hB * 512 + i * 128 + seg * 4));
        }

        GEMM_GROUP(hA, 0)

        // store half B (disjoint SMEM region; GEMM A reads only half hA)
#pragma unroll
        for (int i = 0; i < 4; i++) {
            ln_s += rb[i].x + rb[i].y + rb[i].z + rb[i].w;
            ln_q += rb[i].x*rb[i].x + rb[i].y*rb[i].y + rb[i].z*rb[i].z + rb[i].w*rb[i].w;
            *(float4*)&Ssm[w * 1024 + hB * 512 + i * 128 + seg * 4] = rb[i];
        }

        GEMM_GROUP(hA, 1)

        // LN(t-1) for batch w: warp reduce + publish
#pragma unroll
        for (int d = 16; d >= 1; d >>= 1) {
            ln_s += __shfl_xor_sync(FULL, ln_s, d);
            ln_q += __shfl_xor_sync(FULL, ln_q, d);
        }
        if (l == 0) {
            float mean = ln_s * (1.0f / H_);
            float var  = ln_q * (1.0f / H_) - mean * mean;
            bcast[w * 2 + 0] = mean;
            bcast[w * 2 + 1] = rsqrtf(var + 1e-5f);
        }
        __syncthreads();

        // y(t-1) from register-resident snp (bcast valid until next step's publish)
        {
            float mean = bcast[myb * 2 + 0], rstd = bcast[myb * 2 + 1];
            float y = (snp - mean) * rstd * ga + be;
            out[((size_t)gb * T_ + (t - 1)) * H_ + mych] = y;
        }

        GEMM_GROUP(hB, 0)
        GEMM_GROUP(hB, 1)

        // tail: butterfly reduce-scatter -> update -> store -> fence -> sync -> flag
        float accf[32];
#pragma unroll
        for (int o = 0; o < 32; o++) accf[o] = f2_lo(acc[o]) + f2_hi(acc[o]);
#pragma unroll
        for (int delta = 16; delta >= 1; delta >>= 1) {
            bool up = (l & delta) != 0;
#pragma unroll
            for (int q = 0; q < delta; q++) {
                float send = up ? accf[q] : accf[q + delta];
                float recv = __shfl_xor_sync(FULL, send, delta);
                accf[q] = (up ? accf[q + delta] : accf[q]) + recv;
            }
        }

        float dr = tanhf(uv + accf[0] + bs);
        float sn = dd * snp + (1.0f - dd) * dr;
        __stcg(&g_stt[wslot][gb][mych], sn);
        __threadfence();
        __syncthreads();
        if (tid == 0) atomicAdd(&g_flag[t + 1][g][jc], 1);
        snp = sn;
    }

    // ---------------- final LayerNorm for t = T-1 (state in slot 0) ----------------
    {
        float ln_s = 0.0f, ln_q = 0.0f;
        const float* srow = &g_stt[0][b0 + w][0];
#pragma unroll
        for (int h = 0; h < 2; h++)
#pragma unroll
            for (int i = 0; i < 4; i++) {
                volatile int* fp = &g_flag[T_][g][h * 16 + i * 4 + fseg];
                while (*fp < thr) {}
                float4 r = __ldcg((const float4*)(srow + h * 512 + i * 128 + seg * 4));
                ln_s += r.x + r.y + r.z + r.w;
                ln_q += r.x*r.x + r.y*r.y + r.z*r.z + r.w*r.w;
            }
#pragma unroll
        for (int d = 16; d >= 1; d >>= 1) {
            ln_s += __shfl_xor_sync(FULL, ln_s, d);
            ln_q += __shfl_xor_sync(FULL, ln_q, d);
        }
        if (l == 0) {
            float mean = ln_s * (1.0f / H_);
            float var  = ln_q * (1.0f / H_) - mean * mean;
            bcast[w * 2 + 0] = mean;
            bcast[w * 2 + 1] = rsqrtf(var + 1e-5f);
        }
        __syncthreads();
        float mean = bcast[myb * 2 + 0], rstd = bcast[myb * 2 + 1];
        float y = (snp - mean) * rstd * ga + be;
        out[((size_t)gb * T_ + (T_ - 1)) * H_ + mych] = y;
    }
}

extern "C" void kernel_launch(void* const* d_in, const int* in_sizes, int n_in,
                              void* d_out, int out_size) {
    const float* x     = (const float*)d_in[0];
    const float* Win   = (const float*)d_in[1];
    const float* bin   = (const float*)d_in[2];
    const float* Wst   = (const float*)d_in[3];
    const float* bst   = (const float*)d_in[4];
    const float* decay = (const float*)d_in[5];
    const float* gamma = (const float*)d_in[6];
    const float* beta  = (const float*)d_in[7];
    float* out = (float*)d_out;

    const int smem_bytes = (CHPC_ * H_ + BPG_ * H_ + 40) * sizeof(float);  // ~196.8KB
    cudaFuncSetAttribute(rec_kernel, cudaFuncAttributeMaxDynamicSharedMemorySize, smem_bytes);

    dim3 gg(H_ / 128, (B_ * T_) / 128);
    u_gemm<<<gg, 256>>>(x, Win, bin);
    rec_kernel<<<NCTA_, NTHR_, smem_bytes>>>(Wst, bst, decay, gamma, beta, out);
}